// round 8
// baseline (speedup 1.0000x reference)
#include <cuda_runtime.h>
#include <cstdint>

// ---------------------------------------------------------------------------
// Problem constants
//   feat0_c, feat1_c : [2,128,32,32] fp32
//   feat0_f, feat1_f : [2,128,64,64] fp32
// ---------------------------------------------------------------------------

static const size_t OFF_TF    = 0;
static const size_t OFF_TFC   = 2097152;
static const size_t OFF_C     = 4194304;
static const size_t OFF_CF    = 37748736;
static const size_t OFF_FLOW  = 71303168;
static const size_t OFF_FLOWF = 71319552;

// Scratch (device globals — no allocation allowed)
__device__ float g_cc[2 * 1024 * 1024];          // corr_c  [b][p0c][p1c]   8 MB
__device__ float g_i1[2 * 1024 * 4096];          // (u,v)-upsampled corr_c  33.5 MB (L2-resident)

// softargmax partials (written by fine-GEMM epilogue, merged by flow_reduce)
// flow (rows t=m, source n-blocks j=0..63): [j][b][t]
__device__ float g_f_max[64 * 2 * 4096];
__device__ float g_f_z  [64 * 2 * 4096];
__device__ float g_f_sx [64 * 2 * 4096];
// flow_flip (rows t=n, source m-blocks j2=0..31): [j2][b][t]
__device__ float g_g_max[32 * 2 * 4096];
__device__ float g_g_z  [32 * 2 * 4096];
__device__ float g_g_sx [32 * 2 * 4096];
__device__ float g_g_sy [32 * 2 * 4096];

// ---------------------------------------------------------------------------
// helpers
// ---------------------------------------------------------------------------
__device__ __forceinline__ uint32_t pack_bf16x2(float hi, float lo) {
    uint32_t r;
    asm("cvt.rn.bf16x2.f32 %0, %1, %2;" : "=r"(r) : "f"(hi), "f"(lo));
    return r;
}

__device__ __forceinline__ void mma_bf16(float* d, const uint32_t* a, const uint32_t* b) {
    asm volatile(
        "mma.sync.aligned.m16n8k16.row.col.f32.bf16.bf16.f32 "
        "{%0,%1,%2,%3}, {%4,%5,%6,%7}, {%8,%9}, {%0,%1,%2,%3};\n"
        : "+f"(d[0]), "+f"(d[1]), "+f"(d[2]), "+f"(d[3])
        : "r"(a[0]), "r"(a[1]), "r"(a[2]), "r"(a[3]), "r"(b[0]), "r"(b[1]));
}

__device__ __forceinline__ void ldsm_x4(uint32_t* r, uint32_t saddr) {
    asm volatile("ldmatrix.sync.aligned.m8n8.x4.shared.b16 {%0,%1,%2,%3}, [%4];"
                 : "=r"(r[0]), "=r"(r[1]), "=r"(r[2]), "=r"(r[3]) : "r"(saddr));
}

__device__ __forceinline__ void lerp_weights(int i, int& i0, int& i1, float& w) {
    float f = (float)(i * 31) / 63.0f;   // align_corners scale 31/63, exact at i=0,63
    i0 = (int)f;
    w  = f - (float)i0;
    i1 = min(i0 + 1, 31);
}

__device__ __forceinline__ float warp_max(float v) {
#pragma unroll
    for (int o = 16; o; o >>= 1) v = fmaxf(v, __shfl_xor_sync(0xffffffffu, v, o));
    return v;
}
__device__ __forceinline__ float warp_sum(float v) {
#pragma unroll
    for (int o = 16; o; o >>= 1) v += __shfl_xor_sync(0xffffffffu, v, o);
    return v;
}

// ---------------------------------------------------------------------------
// Correlation GEMM (bf16x3, near-fp32 accuracy), 256 threads / 8 warps,
// 2 CTAs per SM. Block tile 128(m) x 64(n), warp tile 32x32, BK=16,
// mma.m16n8k16 + ldmatrix.x4, double-buffered smem.
// FUSE epilogue: c = 0.5*(rowinterp(g_i1) + corr); writes c + c_flip AND
// per-block online-softmax partials for flow / flow_flip.
// ---------------------------------------------------------------------------
template <int MT, bool FUSE>
__global__ __launch_bounds__(256, 2)
void gemm_corr_kernel(const float* __restrict__ f0, const float* __restrict__ f1,
                      float* __restrict__ outC, float* __restrict__ outF)
{
    extern __shared__ uint32_t smemw[];

    const int b  = blockIdx.z;
    const int m0 = blockIdx.y * 128;
    const int n0 = blockIdx.x * 64;
    const float* A  = f0 + (size_t)b * 128 * MT;  // [K=128][MT]
    const float* Bg = f1 + (size_t)b * 128 * MT;

    const int tid  = threadIdx.x;
    const int warp = tid >> 5, lane = tid & 31;
    const int gid  = lane >> 2, tig = lane & 3;
    const int wm0  = (warp >> 1) * 32;           // 4 warp rows
    const int wn0  = (warp & 1) * 32;            // 2 warp cols

    float acc[2][4][4];
#pragma unroll
    for (int mi = 0; mi < 2; mi++)
#pragma unroll
        for (int j = 0; j < 4; j++)
#pragma unroll
            for (int r = 0; r < 4; r++) acc[mi][j][r] = 0.0f;

    // ---- producer mapping ----
    const int colA = tid & 127;
    const int kgA  = tid >> 7;                   // 0..1
    const int colB = tid & 63;
    const int kgB  = tid >> 6;                   // 0..3

    const uint32_t sbase = (uint32_t)__cvta_generic_to_shared(smemw);

    // ---- consumer ldmatrix row offsets (word units) ----
    const int Lm = lane & 7;
    const int mrowA = ((lane >> 3) & 1) * 8 + Lm;
    const int koffA = (lane >> 4) * 4;
    const uint32_t aoff0 = (uint32_t)((wm0 + mrowA) * 20 + koffA);
    const uint32_t aoff1 = (uint32_t)((wm0 + 16 + mrowA) * 20 + koffA);
    const int nrowB = Lm + ((lane >> 4) << 3);
    const int koffB = ((lane >> 3) & 1) * 4;
    const uint32_t boff0 = (uint32_t)(2560 + (wn0 + nrowB) * 20 + koffB);
    const uint32_t boff1 = (uint32_t)(2560 + (wn0 + 16 + nrowB) * 20 + koffB);

    float a0v0, a0v1, a0v2, a0v3;
    float a1v0, a1v1, a1v2, a1v3;
    float bv0, bv1, bv2, bv3;

#define LOAD_CHUNK(kb)                                                               \
    do {                                                                             \
        const float* Ar0 = A + (size_t)((kb) * 16 + kgA * 4) * MT + m0 + colA;       \
        const float* Ar1 = A + (size_t)((kb) * 16 + (kgA + 2) * 4) * MT + m0 + colA; \
        const float* Br  = Bg + (size_t)((kb) * 16 + kgB * 4) * MT + n0 + colB;      \
        a0v0 = Ar0[0]; a0v1 = Ar0[MT]; a0v2 = Ar0[2 * (size_t)MT]; a0v3 = Ar0[3 * (size_t)MT]; \
        a1v0 = Ar1[0]; a1v1 = Ar1[MT]; a1v2 = Ar1[2 * (size_t)MT]; a1v3 = Ar1[3 * (size_t)MT]; \
        bv0  = Br[0];  bv1  = Br[MT];  bv2  = Br[2 * (size_t)MT];  bv3  = Br[3 * (size_t)MT];  \
    } while (0)

#define PACK_STORE(base_w, v0, v1, v2, v3)                                           \
    do {                                                                             \
        uint32_t h0 = pack_bf16x2(v1, v0);                                           \
        uint32_t h1 = pack_bf16x2(v3, v2);                                           \
        uint32_t l0 = pack_bf16x2(v1 - __uint_as_float(h0 & 0xffff0000u),            \
                                  v0 - __uint_as_float(h0 << 16));                   \
        uint32_t l1 = pack_bf16x2(v3 - __uint_as_float(h1 & 0xffff0000u),            \
                                  v2 - __uint_as_float(h1 << 16));                   \
        *reinterpret_cast<uint2*>(&smemw[(base_w)])     = make_uint2(h0, h1);        \
        *reinterpret_cast<uint2*>(&smemw[(base_w) + 8]) = make_uint2(l0, l1);        \
    } while (0)

#define STORE_CHUNK(bufw)                                                            \
    do {                                                                             \
        PACK_STORE((bufw) + colA * 20 + 2 * kgA,       a0v0, a0v1, a0v2, a0v3);      \
        PACK_STORE((bufw) + colA * 20 + 2 * (kgA + 2), a1v0, a1v1, a1v2, a1v3);      \
        PACK_STORE((bufw) + 2560 + colB * 20 + 2 * kgB, bv0, bv1, bv2, bv3);         \
    } while (0)

    LOAD_CHUNK(0);
    STORE_CHUNK(0u);
    __syncthreads();

    for (int kb = 0; kb < 8; kb++) {
        if (kb < 7) LOAD_CHUNK(kb + 1);

        const uint32_t bw = (uint32_t)(kb & 1) * 3840u;
        uint32_t bh[2][4], bl[2][4];
        ldsm_x4(bh[0], sbase + (bw + boff0) * 4u);
        ldsm_x4(bl[0], sbase + (bw + boff0 + 8u) * 4u);
        ldsm_x4(bh[1], sbase + (bw + boff1) * 4u);
        ldsm_x4(bl[1], sbase + (bw + boff1 + 8u) * 4u);

#pragma unroll
        for (int mi = 0; mi < 2; mi++) {
            uint32_t ah[4], al[4];
            const uint32_t ao = (mi ? aoff1 : aoff0);
            ldsm_x4(ah, sbase + (bw + ao) * 4u);
            ldsm_x4(al, sbase + (bw + ao + 8u) * 4u);
#pragma unroll
            for (int j = 0; j < 4; j++) {
                const uint32_t* bfh = &bh[j >> 1][(j & 1) * 2];
                const uint32_t* bfl = &bl[j >> 1][(j & 1) * 2];
                mma_bf16(acc[mi][j], al, bfh);
                mma_bf16(acc[mi][j], ah, bfl);
                mma_bf16(acc[mi][j], ah, bfh);
            }
        }

        if (kb < 7) STORE_CHUNK((uint32_t)((kb + 1) & 1) * 3840u);
        __syncthreads();
    }
#undef LOAD_CHUNK
#undef PACK_STORE
#undef STORE_CHUNK

    const float sc = 0.08838834764831845f;       // 1/sqrt(128)

    if constexpr (!FUSE) {
        float* out = g_cc + (size_t)b * MT * MT;
        (void)outC; (void)outF;
#pragma unroll
        for (int mi = 0; mi < 2; mi++)
#pragma unroll
            for (int j = 0; j < 4; j++) {
                int r0 = m0 + wm0 + mi * 16 + gid;
                int cc = n0 + wn0 + j * 8 + 2 * tig;
                float2 v0 = make_float2(acc[mi][j][0] * sc, acc[mi][j][1] * sc);
                float2 v1 = make_float2(acc[mi][j][2] * sc, acc[mi][j][3] * sc);
                *reinterpret_cast<float2*>(&out[(size_t)r0 * MT + cc])       = v0;
                *reinterpret_cast<float2*>(&out[(size_t)(r0 + 8) * MT + cc]) = v1;
            }
    } else {
        float* S = reinterpret_cast<float*>(smemw);        // 128 x 65 (33.3 KB)
        float* Y = reinterpret_cast<float*>(smemw) + 8320; // 64 x 68  (17.4 KB)
        const size_t cb = (size_t)b * MT * MT;
        const int h0base = m0 >> 6;

        // --- store corr into S ---
#pragma unroll
        for (int mi = 0; mi < 2; mi++)
#pragma unroll
            for (int j = 0; j < 4; j++) {
                int r0  = wm0 + mi * 16 + gid;
                int col = wn0 + j * 8 + 2 * tig;
                S[r0 * 65 + col]           = acc[mi][j][0] * sc;
                S[r0 * 65 + col + 1]       = acc[mi][j][1] * sc;
                S[(r0 + 8) * 65 + col]     = acc[mi][j][2] * sc;
                S[(r0 + 8) * 65 + col + 1] = acc[mi][j][3] * sc;
            }

        // --- build Y: y-blend of g_i1 rows for 2 h0 values, 32 cx, 64 cols ---
#pragma unroll
        for (int t = 0; t < 4; t++) {
            int e     = tid + t * 256;
            int h0loc = e >> 9;
            int cx    = (e >> 4) & 31;
            int c4    = e & 15;
            int y0, y1; float wy;
            lerp_weights(h0base + h0loc, y0, y1, wy);
            const float4* p0 = reinterpret_cast<const float4*>(
                g_i1 + ((size_t)b * 1024 + y0 * 32 + cx) * 4096 + n0) + c4;
            const float4* p1 = reinterpret_cast<const float4*>(
                g_i1 + ((size_t)b * 1024 + y1 * 32 + cx) * 4096 + n0) + c4;
            float4 a = *p0, bb = *p1;
            float4 v;
            v.x = a.x + wy * (bb.x - a.x);
            v.y = a.y + wy * (bb.y - a.y);
            v.z = a.z + wy * (bb.z - a.z);
            v.w = a.w + wy * (bb.w - a.w);
            *reinterpret_cast<float4*>(&Y[(h0loc * 32 + cx) * 68 + c4 * 4]) = v;
        }
        __syncthreads();

        // --- combine: x-blend + corr, write c, keep combined in S ---
#pragma unroll
        for (int q = 0; q < 8; q++) {
            int idx = tid + q * 256;
            int r   = idx >> 4;
            int cf  = (idx & 15) << 2;
            int h0loc = r >> 6;
            int w0    = r & 63;
            int x0, x1; float wx;
            lerp_weights(w0, x0, x1, wx);
            float4 ya = *reinterpret_cast<const float4*>(&Y[(h0loc * 32 + x0) * 68 + cf]);
            float4 yb = *reinterpret_cast<const float4*>(&Y[(h0loc * 32 + x1) * 68 + cf]);
            float4 ip;
            ip.x = ya.x + wx * (yb.x - ya.x);
            ip.y = ya.y + wx * (yb.y - ya.y);
            ip.z = ya.z + wx * (yb.z - ya.z);
            ip.w = ya.w + wx * (yb.w - ya.w);
            size_t ga = cb + (size_t)(m0 + r) * MT + n0 + cf;
            float4 v;
            v.x = 0.5f * (ip.x + S[r * 65 + cf]);
            v.y = 0.5f * (ip.y + S[r * 65 + cf + 1]);
            v.z = 0.5f * (ip.z + S[r * 65 + cf + 2]);
            v.w = 0.5f * (ip.w + S[r * 65 + cf + 3]);
            *reinterpret_cast<float4*>(outC + ga) = v;
            S[r * 65 + cf]     = v.x;
            S[r * 65 + cf + 1] = v.y;
            S[r * 65 + cf + 2] = v.z;
            S[r * 65 + cf + 3] = v.w;
        }
        __syncthreads();

        // --- transposed rows: c_flip[n][m0..m0+127] ---
#pragma unroll
        for (int jr = 0; jr < 8; jr++) {
            int n = warp * 8 + jr;
            size_t fb = cb + (size_t)(n0 + n) * MT + m0;
#pragma unroll
            for (int q = 0; q < 4; q++) {
                int m = lane + q * 32;            // bank = (m+n)%32 -> conflict-free
                outF[fb + m] = S[m * 65 + n];
            }
        }

        // ------------------------------------------------------------------
        // softargmax partials from S (combined values)
        // ------------------------------------------------------------------
        const float inv63x2 = 2.0f / 63.0f;

        // flow: rows t = m0+rr, source = this block's 64 n-cols (h1 = blockIdx.x const)
        {
            const size_t pb = ((size_t)blockIdx.x * 2 + b) * 4096 + m0;
            const float xn0 = (float)lane * inv63x2 - 1.0f;
            const float xn1 = (float)(lane + 32) * inv63x2 - 1.0f;
#pragma unroll
            for (int rr8 = 0; rr8 < 16; rr8++) {
                int rr = warp * 16 + rr8;
                float v0 = S[rr * 65 + lane];
                float v1 = S[rr * 65 + lane + 32];
                float mx = warp_max(fmaxf(v0, v1));
                float Z = 0.0f, Sx = 0.0f;
                float t0 = (v0 - mx) * 50.0f;
                if (t0 > -25.0f) { float e = __expf(t0); Z += e; Sx += e * xn0; }
                float t1 = (v1 - mx) * 50.0f;
                if (t1 > -25.0f) { float e = __expf(t1); Z += e; Sx += e * xn1; }
                Z  = warp_sum(Z);
                Sx = warp_sum(Sx);
                if (lane == 0) {
                    g_f_max[pb + rr] = mx;
                    g_f_z  [pb + rr] = Z;
                    g_f_sx [pb + rr] = Sx;
                }
            }
        }

        // flow_flip: rows t = n0+nn, source = this block's 128 m-rows
        {
            const size_t pb = ((size_t)blockIdx.y * 2 + b) * 4096 + n0;
            const float yn0 = (float)(h0base)     * inv63x2 - 1.0f;
            const float yn1 = (float)(h0base + 1) * inv63x2 - 1.0f;
#pragma unroll
            for (int nn8 = 0; nn8 < 8; nn8++) {
                int nn = warp * 8 + nn8;
                float v[4];
#pragma unroll
                for (int q = 0; q < 4; q++) v[q] = S[(lane + q * 32) * 65 + nn];
                float mx = warp_max(fmaxf(fmaxf(v[0], v[1]), fmaxf(v[2], v[3])));
                float Z = 0.0f, Sx = 0.0f, Sy = 0.0f;
#pragma unroll
                for (int q = 0; q < 4; q++) {
                    float tt = (v[q] - mx) * 50.0f;
                    if (tt > -25.0f) {
                        float e = __expf(tt);
                        float xn = (float)(lane + (q & 1) * 32) * inv63x2 - 1.0f;
                        Z += e; Sx += e * xn; Sy += e * ((q >> 1) ? yn1 : yn0);
                    }
                }
                Z  = warp_sum(Z);
                Sx = warp_sum(Sx);
                Sy = warp_sum(Sy);
                if (lane == 0) {
                    g_g_max[pb + nn] = mx;
                    g_g_z  [pb + nn] = Z;
                    g_g_sx [pb + nn] = Sx;
                    g_g_sy [pb + nn] = Sy;
                }
            }
        }
    }
}

// ---------------------------------------------------------------------------
// flow_reduce: online-softmax merge of per-block partials -> flow / flow_flip
// grid (16, 2, 2): x*256+tid = t, y = batch, z = 0 flow / 1 flow_flip
// ---------------------------------------------------------------------------
__global__ __launch_bounds__(256)
void flow_reduce_kernel(float* __restrict__ fl, float* __restrict__ flf)
{
    const int t = blockIdx.x * 256 + threadIdx.x;
    const int b = blockIdx.y;
    const float inv63x2 = 2.0f / 63.0f;

    float M = -1e30f, Z = 0.0f, Sx = 0.0f, Sy = 0.0f;

    if (blockIdx.z == 0) {
        for (int j = 0; j < 64; j++) {
            size_t idx = ((size_t)j * 2 + b) * 4096 + t;
            float mj = g_f_max[idx], zj = g_f_z[idx], sxj = g_f_sx[idx];
            float ynj = (float)j * inv63x2 - 1.0f;
            if (mj > M) {
                float s = __expf((M - mj) * 50.0f);
                Z *= s; Sx *= s; Sy *= s; M = mj;
            }
            float w = __expf((mj - M) * 50.0f);
            Z += w * zj; Sx += w * sxj; Sy += w * ynj * zj;
        }
        float gx = Sx / Z, gy = Sy / Z;
        float w = (float)(t & 63), h = (float)(t >> 6);
        fl[(size_t)b * 8192 + t]        = (gx + 1.0f) * 31.5f - w;
        fl[(size_t)b * 8192 + 4096 + t] = (gy + 1.0f) * 31.5f - h;
    } else {
        for (int j = 0; j < 32; j++) {
            size_t idx = ((size_t)j * 2 + b) * 4096 + t;
            float mj = g_g_max[idx], zj = g_g_z[idx];
            float sxj = g_g_sx[idx], syj = g_g_sy[idx];
            if (mj > M) {
                float s = __expf((M - mj) * 50.0f);
                Z *= s; Sx *= s; Sy *= s; M = mj;
            }
            float w = __expf((mj - M) * 50.0f);
            Z += w * zj; Sx += w * sxj; Sy += w * syj;
        }
        float gx = Sx / Z, gy = Sy / Z;
        float w = (float)(t & 63), h = (float)(t >> 6);
        flf[(size_t)b * 8192 + t]        = (gx + 1.0f) * 31.5f - w;
        flf[(size_t)b * 8192 + 4096 + t] = (gy + 1.0f) * 31.5f - h;
    }
}

// ---------------------------------------------------------------------------
// trans_features_coarse: bilinear 32->64 (align_corners) per channel
// ---------------------------------------------------------------------------
__global__ __launch_bounds__(256)
void resize_coarse_kernel(const float* __restrict__ a, const float* __restrict__ bsrc,
                          float* __restrict__ out)
{
    __shared__ float s[1024];
    int blk = blockIdx.x;                        // 0..511
    int bb = blk >> 8, ii = (blk >> 7) & 1, ch = blk & 127;
    const float* in = (ii ? bsrc : a) + ((size_t)bb * 128 + ch) * 1024;
    float* o = out + (((size_t)bb * 2 + ii) * 128 + ch) * 4096;
    int tid = threadIdx.x;
#pragma unroll
    for (int q = 0; q < 4; q++) s[tid + q * 256] = in[tid + q * 256];
    __syncthreads();
#pragma unroll
    for (int q = 0; q < 16; q++) {
        int oi = tid + q * 256;
        int oy = oi >> 6, ox = oi & 63;
        int y0, y1, x0, x1; float wy, wx;
        lerp_weights(oy, y0, y1, wy);
        lerp_weights(ox, x0, x1, wx);
        float v = (1.0f - wy) * ((1.0f - wx) * s[y0 * 32 + x0] + wx * s[y0 * 32 + x1])
                +         wy  * ((1.0f - wx) * s[y1 * 32 + x0] + wx * s[y1 * 32 + x1]);
        o[oi] = v;
    }
}

// ---------------------------------------------------------------------------
// interp pass A: per (b,p0c) row, upsample (u,v) 32x32 -> 64x64
// ---------------------------------------------------------------------------
__global__ __launch_bounds__(256)
void interpA_kernel()
{
    __shared__ float s[1024];
    int blk = blockIdx.x;                        // 0..2047 = b*1024 + p0c
    const float* in = g_cc + (size_t)blk * 1024;
    float* o = g_i1 + (size_t)blk * 4096;
    int tid = threadIdx.x;
#pragma unroll
    for (int q = 0; q < 4; q++) s[tid + q * 256] = in[tid + q * 256];
    __syncthreads();
#pragma unroll
    for (int q = 0; q < 16; q++) {
        int oi = tid + q * 256;
        int oy = oi >> 6, ox = oi & 63;
        int y0, y1, x0, x1; float wy, wx;
        lerp_weights(oy, y0, y1, wy);
        lerp_weights(ox, x0, x1, wx);
        float v = (1.0f - wy) * ((1.0f - wx) * s[y0 * 32 + x0] + wx * s[y0 * 32 + x1])
                +         wy  * ((1.0f - wx) * s[y1 * 32 + x0] + wx * s[y1 * 32 + x1]);
        o[oi] = v;
    }
}

// ---------------------------------------------------------------------------
// launch
// ---------------------------------------------------------------------------
extern "C" void kernel_launch(void* const* d_in, const int* in_sizes, int n_in,
                              void* d_out, int out_size)
{
    (void)in_sizes; (void)n_in; (void)out_size;
    const float* f0c = (const float*)d_in[0];
    const float* f1c = (const float*)d_in[1];
    const float* f0f = (const float*)d_in[2];
    const float* f1f = (const float*)d_in[3];
    float* out = (float*)d_out;

    cudaFuncSetAttribute(gemm_corr_kernel<4096, true>,
                         cudaFuncAttributeMaxDynamicSharedMemorySize, 50688);

    // trans_features = stack([feat0_f, feat1_f], axis=1)
    const size_t chunk = (size_t)128 * 4096;
    cudaMemcpyAsync(out + OFF_TF + 0 * chunk, f0f,         chunk * 4, cudaMemcpyDeviceToDevice, 0);
    cudaMemcpyAsync(out + OFF_TF + 1 * chunk, f1f,         chunk * 4, cudaMemcpyDeviceToDevice, 0);
    cudaMemcpyAsync(out + OFF_TF + 2 * chunk, f0f + chunk, chunk * 4, cudaMemcpyDeviceToDevice, 0);
    cudaMemcpyAsync(out + OFF_TF + 3 * chunk, f1f + chunk, chunk * 4, cudaMemcpyDeviceToDevice, 0);

    resize_coarse_kernel<<<512, 256>>>(f0c, f1c, out + OFF_TFC);

    gemm_corr_kernel<1024, false><<<dim3(16, 8, 2), 256, 30720>>>(f0c, f1c, nullptr, nullptr);
    interpA_kernel<<<2048, 256>>>();
    gemm_corr_kernel<4096, true><<<dim3(64, 32, 2), 256, 50688>>>(f0f, f1f, out + OFF_C, out + OFF_CF);

    flow_reduce_kernel<<<dim3(16, 2, 2), 256>>>(out + OFF_FLOW, out + OFF_FLOWF);
}